// round 6
// baseline (speedup 1.0000x reference)
#include <cuda_runtime.h>
#include <cuda_bf16.h>
#include <stdint.h>

#define HEADS 16
#define MDIM 4096
#define NDIM 4096
#define KDIM 64
#define QBLK 32

// Dequantized-exact bf16 operands in PERMUTED fragment layout.
// Each logical row (m for lhs, n for rhs-transposed) is 64 bf16 = 128B,
// stored as 4 chunks of 32B: chunk c holds k = 2c+{0,1}+8j for j=0..7
// (pair j at byte offset c*32 + j*4). This is exactly the per-lane data
// order of mma.m16n8k16 A/B fragments, so the GEMM loads fragments with
// coalesced LDG.128 straight from global -- no smem, no ldmatrix.
static __device__ __align__(128) __nv_bfloat16 g_lhs[(size_t)HEADS * MDIM * KDIM];
static __device__ __align__(128) __nv_bfloat16 g_rhs[(size_t)HEADS * NDIM * KDIM];

// ===========================================================================
// Quant: one thread per 32-block (full shared-exponent block in registers).
// q = clip(rint(x * 2^(7-e)), -128, 127); out = q * 2^(e-7); exact in bf16.
// Writes its half-row into the permuted layout: 4x uint4, chunk c at
// c*32 + half*16, pairs (v[2c+8j'], v[2c+8j'+1]) j'=0..3.
// ===========================================================================
__device__ __forceinline__ void quant_block32(float v[QBLK]) {
    float ma = 0.f;
#pragma unroll
    for (int i = 0; i < QBLK; i++) ma = fmaxf(ma, fabsf(v[i]));
    if (ma > 0.f) {
        int e = ilogbf(fmaxf(ma, 1e-38f));       // floor(log2(.)) exactly
        float scale = exp2f((float)(7 - e));     // exact power of two
        float step  = exp2f((float)(e - 7));
#pragma unroll
        for (int i = 0; i < QBLK; i++) {
            float q = rintf(v[i] * scale);       // round-half-even
            q = fminf(fmaxf(q, -128.f), 127.f);
            v[i] = q * step;                     // exact
        }
    } else {
#pragma unroll
        for (int i = 0; i < QBLK; i++) v[i] = 0.f;
    }
}

__device__ __forceinline__ void store_perm32(__nv_bfloat16* row, int half,
                                             const float v[QBLK]) {
#pragma unroll
    for (int c = 0; c < 4; c++) {
        uint32_t p[4];
#pragma unroll
        for (int j = 0; j < 4; j++) {
            __nv_bfloat162 h2 = __floats2bfloat162_rn(v[2 * c + 8 * j],
                                                      v[2 * c + 8 * j + 1]);
            p[j] = *reinterpret_cast<uint32_t*>(&h2);
        }
        *reinterpret_cast<uint4*>(reinterpret_cast<char*>(row) + c * 32 + half * 16) =
            make_uint4(p[0], p[1], p[2], p[3]);
    }
}

#define QL_BLOCKS 512   // 131072 threads: 65536 lhs rows x 2 halves
#define QR_BLOCKS 512

__global__ void __launch_bounds__(256) quant_all_kernel(
    const float* __restrict__ lhs, const float* __restrict__ rhs) {
    if (blockIdx.x < QL_BLOCKS) {
        // lhs [h][m][64]: thread owns one contiguous 32-block.
        int t = blockIdx.x * 256 + threadIdx.x;
        int half = t & 1;
        int rowi = t >> 1;                        // h*4096 + m
        const float4* src = reinterpret_cast<const float4*>(
            lhs + (size_t)rowi * KDIM + half * QBLK);
        float v[QBLK];
#pragma unroll
        for (int j = 0; j < 8; j++) {
            float4 f = __ldg(src + j);
            v[4 * j] = f.x; v[4 * j + 1] = f.y; v[4 * j + 2] = f.z; v[4 * j + 3] = f.w;
        }
        quant_block32(v);
        store_perm32(g_lhs + (size_t)rowi * KDIM, half, v);
    } else {
        // rhs [h][k=64][n]: block runs along k (stride NDIM); transpose on write.
        int t = (blockIdx.x - QL_BLOCKS) * 256 + threadIdx.x;
        int half = t & 1;
        int pair = t >> 1;
        int n = pair & (NDIM - 1);
        int h = pair >> 12;
        const float* src = rhs + ((size_t)h * KDIM + half * QBLK) * NDIM + n;
        float v[QBLK];
#pragma unroll
        for (int k = 0; k < QBLK; k++) v[k] = __ldg(src + (size_t)k * NDIM);
        quant_block32(v);
        store_perm32(g_rhs + ((size_t)h * NDIM + n) * KDIM, half, v);
    }
}

// ===========================================================================
// GEMM: out[h][m][n] = sum_k A[m][k]*B[n][k]; bf16 mma, fragments via direct
// coalesced LDG.128 from the permuted layout. Zero shared memory.
// 128x128 CTA tile, 8 warps = 4(m) x 2(n), warp tile 32x64.
// ===========================================================================
__global__ void __launch_bounds__(256) bfp_gemm_kernel(float* __restrict__ out) {
    const int h  = blockIdx.z;
    const int bm = blockIdx.y, bn = blockIdx.x;
    const int tid  = threadIdx.x;
    const int lane = tid & 31;
    const int wid  = tid >> 5;
    const int wm   = (wid >> 1) * 32;   // warp row base
    const int wn   = (wid & 1) * 64;    // warp col base
    const int g    = lane >> 2;         // groupID
    const int t4   = lane & 3;          // threadID_in_group (selects chunk)

    const __nv_bfloat16* Ab = g_lhs + ((size_t)h * MDIM + bm * 128) * KDIM;
    const __nv_bfloat16* Bb = g_rhs + ((size_t)h * NDIM + bn * 128) * KDIM;

    // A fragments for all K=64: per mt, low rows (g) and high rows (g+8),
    // 32B chunk each. aLo[mt][j]/aHi[mt][j]: pair j = 2*ks + (0:k, 1:k+8).
    uint32_t aLo[2][8], aHi[2][8];
#pragma unroll
    for (int mt = 0; mt < 2; mt++) {
        const uint4* pLo = reinterpret_cast<const uint4*>(
            Ab + (size_t)(wm + mt * 16 + g) * KDIM) + t4 * 2;
        const uint4* pHi = reinterpret_cast<const uint4*>(
            Ab + (size_t)(wm + mt * 16 + g + 8) * KDIM) + t4 * 2;
        uint4 l0 = __ldg(pLo), l1 = __ldg(pLo + 1);
        uint4 h0 = __ldg(pHi), h1 = __ldg(pHi + 1);
        aLo[mt][0] = l0.x; aLo[mt][1] = l0.y; aLo[mt][2] = l0.z; aLo[mt][3] = l0.w;
        aLo[mt][4] = l1.x; aLo[mt][5] = l1.y; aLo[mt][6] = l1.z; aLo[mt][7] = l1.w;
        aHi[mt][0] = h0.x; aHi[mt][1] = h0.y; aHi[mt][2] = h0.z; aHi[mt][3] = h0.w;
        aHi[mt][4] = h1.x; aHi[mt][5] = h1.y; aHi[mt][6] = h1.z; aHi[mt][7] = h1.w;
    }

    float acc[2][8][4];
#pragma unroll
    for (int mt = 0; mt < 2; mt++)
#pragma unroll
        for (int nt = 0; nt < 8; nt++)
#pragma unroll
            for (int i = 0; i < 4; i++) acc[mt][nt][i] = 0.f;

#pragma unroll
    for (int nt = 0; nt < 8; nt++) {
        // B fragment row n = wn + nt*8 + g, 32B chunk: bb[j], j = 2*ks + reg.
        const uint4* pB = reinterpret_cast<const uint4*>(
            Bb + (size_t)(wn + nt * 8 + g) * KDIM) + t4 * 2;
        uint4 b0 = __ldg(pB), b1 = __ldg(pB + 1);
        uint32_t bb[8] = {b0.x, b0.y, b0.z, b0.w, b1.x, b1.y, b1.z, b1.w};
#pragma unroll
        for (int ks = 0; ks < 4; ks++) {
#pragma unroll
            for (int mt = 0; mt < 2; mt++) {
                asm volatile(
                    "mma.sync.aligned.m16n8k16.row.col.f32.bf16.bf16.f32 "
                    "{%0,%1,%2,%3}, {%4,%5,%6,%7}, {%8,%9}, {%0,%1,%2,%3};\n"
                    : "+f"(acc[mt][nt][0]), "+f"(acc[mt][nt][1]),
                      "+f"(acc[mt][nt][2]), "+f"(acc[mt][nt][3])
                    : "r"(aLo[mt][2 * ks]), "r"(aHi[mt][2 * ks]),
                      "r"(aLo[mt][2 * ks + 1]), "r"(aHi[mt][2 * ks + 1]),
                      "r"(bb[2 * ks]), "r"(bb[2 * ks + 1]));
            }
        }
    }

    // Streaming stores: 32B-sector-aligned float2 per lane, evict-first.
    float* gO = out + (size_t)h * MDIM * NDIM + (size_t)(bm * 128) * NDIM + bn * 128;
#pragma unroll
    for (int mt = 0; mt < 2; mt++) {
#pragma unroll
        for (int nt = 0; nt < 8; nt++) {
            int r0 = wm + mt * 16 + g;
            int c0 = wn + nt * 8 + t4 * 2;
            __stcs(reinterpret_cast<float2*>(&gO[(size_t)r0 * NDIM + c0]),
                   make_float2(acc[mt][nt][0], acc[mt][nt][1]));
            __stcs(reinterpret_cast<float2*>(&gO[(size_t)(r0 + 8) * NDIM + c0]),
                   make_float2(acc[mt][nt][2], acc[mt][nt][3]));
        }
    }
}

extern "C" void kernel_launch(void* const* d_in, const int* in_sizes, int n_in,
                              void* d_out, int out_size) {
    (void)in_sizes; (void)n_in; (void)out_size;
    const float* lhs = (const float*)d_in[0];  // [1,16,4096,64]
    const float* rhs = (const float*)d_in[1];  // [1,16,64,4096]
    float* out = (float*)d_out;                // [1,16,4096,4096]

    quant_all_kernel<<<QL_BLOCKS + QR_BLOCKS, 256>>>(lhs, rhs);

    dim3 grid(NDIM / 128, MDIM / 128, HEADS);
    bfp_gemm_kernel<<<grid, 256>>>(out);
}

// round 7
// speedup vs baseline: 1.0394x; 1.0394x over previous
#include <cuda_runtime.h>
#include <cuda_bf16.h>
#include <stdint.h>

#define HEADS 16
#define MDIM 4096
#define NDIM 4096
#define KDIM 64
#define QBLK 32

// Quantized (dequantized-to-bf16, exact) operands. rhs stored transposed: [h][n][k].
static __device__ __nv_bfloat16 g_lhs[(size_t)HEADS * MDIM * KDIM];
static __device__ __nv_bfloat16 g_rhs[(size_t)HEADS * NDIM * KDIM];

// ===========================================================================
// Quant phase (R3-proven): fused lhs+rhs BFP quantization, bf16-exact output.
// ===========================================================================
__device__ __forceinline__ void quant_half16(float v[16]) {
    float ma = 0.f;
#pragma unroll
    for (int i = 0; i < 16; i++) ma = fmaxf(ma, fabsf(v[i]));
    ma = fmaxf(ma, __shfl_xor_sync(0xFFFFFFFFu, ma, 1));  // full 32-block max
    if (ma > 0.f) {
        int e = ilogbf(fmaxf(ma, 1e-38f));       // floor(log2(.)) exactly
        float scale = exp2f((float)(7 - e));     // exact power of two
        float step  = exp2f((float)(e - 7));
#pragma unroll
        for (int i = 0; i < 16; i++) {
            float q = rintf(v[i] * scale);       // round-half-even
            q = fminf(fmaxf(q, -128.f), 127.f);
            v[i] = q * step;                     // exact
        }
    } else {
#pragma unroll
        for (int i = 0; i < 16; i++) v[i] = 0.f;
    }
}

__device__ __forceinline__ void pack_store16(__nv_bfloat16* dst, const float v[16]) {
    uint32_t pk[8];
#pragma unroll
    for (int j = 0; j < 8; j++) {
        __nv_bfloat162 h2 = __floats2bfloat162_rn(v[2 * j], v[2 * j + 1]);
        pk[j] = *reinterpret_cast<uint32_t*>(&h2);
    }
    uint4* d4 = reinterpret_cast<uint4*>(dst);
    d4[0] = make_uint4(pk[0], pk[1], pk[2], pk[3]);
    d4[1] = make_uint4(pk[4], pk[5], pk[6], pk[7]);
}

#define QL_BLOCKS 1024
#define QR_BLOCKS 1024

__global__ void __launch_bounds__(256) quant_all_kernel(
    const float* __restrict__ lhs, const float* __restrict__ rhs) {
    if (blockIdx.x < QL_BLOCKS) {
        size_t t = blockIdx.x * (size_t)blockDim.x + threadIdx.x;
        const float4* src = reinterpret_cast<const float4*>(lhs + t * 16);
        float v[16];
#pragma unroll
        for (int j = 0; j < 4; j++) {
            float4 f = __ldg(src + j);
            v[4 * j] = f.x; v[4 * j + 1] = f.y; v[4 * j + 2] = f.z; v[4 * j + 3] = f.w;
        }
        quant_half16(v);
        pack_store16(g_lhs + t * 16, v);
    } else {
        int t    = (blockIdx.x - QL_BLOCKS) * blockDim.x + threadIdx.x;
        int half = t & 1;
        int pair = t >> 1;
        int c  = pair & (NDIM - 1);
        int kb = (pair >> 12) & 1;
        int h  = pair >> 13;
        const float* src = rhs + ((size_t)h * KDIM + kb * QBLK + half * 16) * NDIM + c;
        float v[16];
#pragma unroll
        for (int k = 0; k < 16; k++) v[k] = __ldg(src + (size_t)k * NDIM);
        quant_half16(v);
        pack_store16(g_rhs + (((size_t)h * NDIM + c) * KDIM + kb * QBLK + half * 16), v);
    }
}

// ===========================================================================
// GEMM: out[h][m][n] = sum_k A[m][k]*B[n][k]; bf16 mma, fp32 acc.
// CTA tile 128(m) x 256(n), K=64 fully resident. 8 warps = 2(m) x 4(n),
// warp tile 64x64 (halves ldmatrix redundancy vs 32x64).
// Operands staged via cp.async into XOR-swizzled 128B rows (one L1 pass).
// ===========================================================================
#define BM 128
#define BN 256
#define SM_B_OFF 16384                 // A: 128 rows * 128B
#define GEMM_SMEM (SM_B_OFF + BN * 128)  // 49152 B

__global__ void __launch_bounds__(256, 1) bfp_gemm_kernel(float* __restrict__ out) {
    extern __shared__ char smem[];
    const uint32_t sbase = (uint32_t)__cvta_generic_to_shared(smem);

    const int h  = blockIdx.z;
    const int bm = blockIdx.y, bn = blockIdx.x;
    const __nv_bfloat16* gA = g_lhs + ((size_t)h * MDIM + bm * BM) * KDIM;
    const __nv_bfloat16* gB = g_rhs + ((size_t)h * NDIM + bn * BN) * KDIM;
    const int tid = threadIdx.x;

    // Stage A (128 rows) + B (256 rows), 128B each, via cp.async.
    // Swizzle: 16B unit j -> j ^ (row & 7): conflict-free ldmatrix phases.
#pragma unroll
    for (int i = 0; i < 12; i++) {
        int idx = i * 256 + tid;        // 0..3071
        int row = idx >> 3, j = idx & 7;
        int sw = j ^ (row & 7);
        uint32_t dst;
        const char* src;
        if (row < BM) {
            dst = sbase + row * 128 + sw * 16;
            src = reinterpret_cast<const char*>(gA + (size_t)row * KDIM) + j * 16;
        } else {
            int r = row - BM;
            dst = sbase + SM_B_OFF + r * 128 + sw * 16;
            src = reinterpret_cast<const char*>(gB + (size_t)r * KDIM) + j * 16;
        }
        asm volatile("cp.async.cg.shared.global [%0], [%1], 16;\n"
                     :: "r"(dst), "l"(src));
    }
    asm volatile("cp.async.commit_group;\n" ::: "memory");
    asm volatile("cp.async.wait_group 0;\n" ::: "memory");
    __syncthreads();

    const int lane = tid & 31;
    const int wid  = tid >> 5;
    const int wm   = (wid & 1) * 64;    // 2 m-warps
    const int wn   = (wid >> 1) * 64;   // 4 n-warps
    const int g    = lane >> 2;
    const int t4   = lane & 3;

    float acc[4][8][4];
#pragma unroll
    for (int mt = 0; mt < 4; mt++)
#pragma unroll
        for (int nt = 0; nt < 8; nt++)
#pragma unroll
            for (int i = 0; i < 4; i++) acc[mt][nt][i] = 0.f;

#pragma unroll
    for (int ks = 0; ks < 4; ks++) {
        uint32_t a[4][4];
#pragma unroll
        for (int mt = 0; mt < 4; mt++) {
            int row = wm + mt * 16 + (lane & 15);
            int cu  = (ks * 2 + (lane >> 4)) ^ (row & 7);
            uint32_t addr = sbase + row * 128 + cu * 16;
            asm volatile("ldmatrix.sync.aligned.m8n8.x4.shared.b16 {%0,%1,%2,%3}, [%4];\n"
                         : "=r"(a[mt][0]), "=r"(a[mt][1]), "=r"(a[mt][2]), "=r"(a[mt][3])
                         : "r"(addr));
        }
#pragma unroll
        for (int nt = 0; nt < 8; nt++) {
            int row = wn + nt * 8 + (lane & 7);
            int cu  = (ks * 2 + ((lane >> 3) & 1)) ^ (row & 7);
            uint32_t addr = sbase + SM_B_OFF + row * 128 + cu * 16;
            uint32_t b0, b1;
            asm volatile("ldmatrix.sync.aligned.m8n8.x2.shared.b16 {%0,%1}, [%2];\n"
                         : "=r"(b0), "=r"(b1) : "r"(addr));
#pragma unroll
            for (int mt = 0; mt < 4; mt++) {
                asm volatile(
                    "mma.sync.aligned.m16n8k16.row.col.f32.bf16.bf16.f32 "
                    "{%0,%1,%2,%3}, {%4,%5,%6,%7}, {%8,%9}, {%0,%1,%2,%3};\n"
                    : "+f"(acc[mt][nt][0]), "+f"(acc[mt][nt][1]),
                      "+f"(acc[mt][nt][2]), "+f"(acc[mt][nt][3])
                    : "r"(a[mt][0]), "r"(a[mt][1]), "r"(a[mt][2]), "r"(a[mt][3]),
                      "r"(b0), "r"(b1));
            }
        }
    }

    // Streaming stores: 32B-sector-aligned float2 per lane, evict-first.
    float* gO = out + (size_t)h * MDIM * NDIM + (size_t)(bm * BM) * NDIM + bn * BN;
#pragma unroll
    for (int mt = 0; mt < 4; mt++) {
#pragma unroll
        for (int nt = 0; nt < 8; nt++) {
            int r0 = wm + mt * 16 + g;
            int c0 = wn + nt * 8 + t4 * 2;
            __stcs(reinterpret_cast<float2*>(&gO[(size_t)r0 * NDIM + c0]),
                   make_float2(acc[mt][nt][0], acc[mt][nt][1]));
            __stcs(reinterpret_cast<float2*>(&gO[(size_t)(r0 + 8) * NDIM + c0]),
                   make_float2(acc[mt][nt][2], acc[mt][nt][3]));
        }
    }
}

extern "C" void kernel_launch(void* const* d_in, const int* in_sizes, int n_in,
                              void* d_out, int out_size) {
    (void)in_sizes; (void)n_in; (void)out_size;
    const float* lhs = (const float*)d_in[0];  // [1,16,4096,64]
    const float* rhs = (const float*)d_in[1];  // [1,16,64,4096]
    float* out = (float*)d_out;                // [1,16,4096,4096]

    quant_all_kernel<<<QL_BLOCKS + QR_BLOCKS, 256>>>(lhs, rhs);

    static bool attr_done = false;
    if (!attr_done) {
        cudaFuncSetAttribute(bfp_gemm_kernel,
                             cudaFuncAttributeMaxDynamicSharedMemorySize, GEMM_SMEM);
        attr_done = true;
    }
    dim3 grid(NDIM / BN, MDIM / BM, HEADS);
    bfp_gemm_kernel<<<grid, 256, GEMM_SMEM>>>(out);
}

// round 8
// speedup vs baseline: 1.2292x; 1.1826x over previous
#include <cuda_runtime.h>
#include <cuda_bf16.h>
#include <stdint.h>

#define HEADS 16
#define MDIM 4096
#define NDIM 4096
#define KDIM 64
#define QBLK 32

// Quantized (dequantized-to-bf16, exact) operands. rhs stored transposed: [h][n][k].
static __device__ __nv_bfloat16 g_lhs[(size_t)HEADS * MDIM * KDIM];
static __device__ __nv_bfloat16 g_rhs[(size_t)HEADS * NDIM * KDIM];

// ===========================================================================
// Quant phase (R3-proven): fused lhs+rhs BFP quantization, bf16-exact output.
// ===========================================================================
__device__ __forceinline__ void quant_half16(float v[16]) {
    float ma = 0.f;
#pragma unroll
    for (int i = 0; i < 16; i++) ma = fmaxf(ma, fabsf(v[i]));
    ma = fmaxf(ma, __shfl_xor_sync(0xFFFFFFFFu, ma, 1));  // full 32-block max
    if (ma > 0.f) {
        int e = ilogbf(fmaxf(ma, 1e-38f));       // floor(log2(.)) exactly
        float scale = exp2f((float)(7 - e));     // exact power of two
        float step  = exp2f((float)(e - 7));
#pragma unroll
        for (int i = 0; i < 16; i++) {
            float q = rintf(v[i] * scale);       // round-half-even
            q = fminf(fmaxf(q, -128.f), 127.f);
            v[i] = q * step;                     // exact
        }
    } else {
#pragma unroll
        for (int i = 0; i < 16; i++) v[i] = 0.f;
    }
}

__device__ __forceinline__ void pack_store16(__nv_bfloat16* dst, const float v[16]) {
    uint32_t pk[8];
#pragma unroll
    for (int j = 0; j < 8; j++) {
        __nv_bfloat162 h2 = __floats2bfloat162_rn(v[2 * j], v[2 * j + 1]);
        pk[j] = *reinterpret_cast<uint32_t*>(&h2);
    }
    uint4* d4 = reinterpret_cast<uint4*>(dst);
    d4[0] = make_uint4(pk[0], pk[1], pk[2], pk[3]);
    d4[1] = make_uint4(pk[4], pk[5], pk[6], pk[7]);
}

#define QL_BLOCKS 1024
#define QR_BLOCKS 1024

__global__ void __launch_bounds__(256) quant_all_kernel(
    const float* __restrict__ lhs, const float* __restrict__ rhs) {
    if (blockIdx.x < QL_BLOCKS) {
        size_t t = blockIdx.x * (size_t)blockDim.x + threadIdx.x;
        const float4* src = reinterpret_cast<const float4*>(lhs + t * 16);
        float v[16];
#pragma unroll
        for (int j = 0; j < 4; j++) {
            float4 f = __ldg(src + j);
            v[4 * j] = f.x; v[4 * j + 1] = f.y; v[4 * j + 2] = f.z; v[4 * j + 3] = f.w;
        }
        quant_half16(v);
        pack_store16(g_lhs + t * 16, v);
    } else {
        int t    = (blockIdx.x - QL_BLOCKS) * blockDim.x + threadIdx.x;
        int half = t & 1;
        int pair = t >> 1;
        int c  = pair & (NDIM - 1);
        int kb = (pair >> 12) & 1;
        int h  = pair >> 13;
        const float* src = rhs + ((size_t)h * KDIM + kb * QBLK + half * 16) * NDIM + c;
        float v[16];
#pragma unroll
        for (int k = 0; k < 16; k++) v[k] = __ldg(src + (size_t)k * NDIM);
        quant_half16(v);
        pack_store16(g_rhs + (((size_t)h * NDIM + c) * KDIM + kb * QBLK + half * 16), v);
    }
}

// ===========================================================================
// GEMM: out[h][m][n] = sum_k A[m][k]*B[n][k]; bf16 mma, fp32 acc.
// CTA tile 128x128, K=64 fully resident. 8 warps = 2(m) x 4(n), warp 64x32
// (acc 64 regs -> ~115 regs total -> 2 CTAs/SM). cp.async staging (one L1
// pass), XOR-swizzled 128B rows, __stcs epilogue.
// ===========================================================================
__global__ void __launch_bounds__(256, 2) bfp_gemm_kernel(float* __restrict__ out) {
    __shared__ __align__(128) char smem[32768];   // A: 16KB, B: 16KB
    const uint32_t sbase = (uint32_t)__cvta_generic_to_shared(smem);
    const uint32_t sB = sbase + 16384;

    const int h  = blockIdx.z;
    const int bm = blockIdx.y, bn = blockIdx.x;
    const __nv_bfloat16* gA = g_lhs + ((size_t)h * MDIM + bm * 128) * KDIM;
    const __nv_bfloat16* gB = g_rhs + ((size_t)h * NDIM + bn * 128) * KDIM;
    const int tid = threadIdx.x;

    // Stage A + B (128 rows x 128B each) via cp.async, 16B units.
    // Swizzle: unit j -> j ^ (row & 7) -> conflict-free ldmatrix phases.
#pragma unroll
    for (int i = 0; i < 4; i++) {
        int idx = i * 256 + tid;        // 0..1023 per operand
        int row = idx >> 3, j = idx & 7;
        int sw = j ^ (row & 7);
        uint32_t dstA = sbase + row * 128 + sw * 16;
        const char* srcA = reinterpret_cast<const char*>(gA + (size_t)row * KDIM) + j * 16;
        asm volatile("cp.async.cg.shared.global [%0], [%1], 16;\n" :: "r"(dstA), "l"(srcA));
        uint32_t dstB = sB + row * 128 + sw * 16;
        const char* srcB = reinterpret_cast<const char*>(gB + (size_t)row * KDIM) + j * 16;
        asm volatile("cp.async.cg.shared.global [%0], [%1], 16;\n" :: "r"(dstB), "l"(srcB));
    }
    asm volatile("cp.async.commit_group;\n" ::: "memory");
    asm volatile("cp.async.wait_group 0;\n" ::: "memory");
    __syncthreads();

    const int lane = tid & 31;
    const int wid  = tid >> 5;
    const int wm   = (wid & 1) * 64;    // 2 m-warps, warp covers 64 rows
    const int wn   = (wid >> 1) * 32;   // 4 n-warps, warp covers 32 cols
    const int g    = lane >> 2;
    const int t4   = lane & 3;

    float acc[4][4][4];
#pragma unroll
    for (int mt = 0; mt < 4; mt++)
#pragma unroll
        for (int nt = 0; nt < 4; nt++)
#pragma unroll
            for (int i = 0; i < 4; i++) acc[mt][nt][i] = 0.f;

#pragma unroll
    for (int ks = 0; ks < 4; ks++) {
        uint32_t a[4][4];
#pragma unroll
        for (int mt = 0; mt < 4; mt++) {
            int row = wm + mt * 16 + (lane & 15);
            int cu  = (ks * 2 + (lane >> 4)) ^ (row & 7);
            uint32_t addr = sbase + row * 128 + cu * 16;
            asm volatile("ldmatrix.sync.aligned.m8n8.x4.shared.b16 {%0,%1,%2,%3}, [%4];\n"
                         : "=r"(a[mt][0]), "=r"(a[mt][1]), "=r"(a[mt][2]), "=r"(a[mt][3])
                         : "r"(addr));
        }
#pragma unroll
        for (int nt = 0; nt < 4; nt++) {
            int row = wn + nt * 8 + (lane & 7);
            int cu  = (ks * 2 + ((lane >> 3) & 1)) ^ (row & 7);
            uint32_t addr = sB + row * 128 + cu * 16;
            uint32_t b0, b1;
            asm volatile("ldmatrix.sync.aligned.m8n8.x2.shared.b16 {%0,%1}, [%2];\n"
                         : "=r"(b0), "=r"(b1) : "r"(addr));
#pragma unroll
            for (int mt = 0; mt < 4; mt++) {
                asm volatile(
                    "mma.sync.aligned.m16n8k16.row.col.f32.bf16.bf16.f32 "
                    "{%0,%1,%2,%3}, {%4,%5,%6,%7}, {%8,%9}, {%0,%1,%2,%3};\n"
                    : "+f"(acc[mt][nt][0]), "+f"(acc[mt][nt][1]),
                      "+f"(acc[mt][nt][2]), "+f"(acc[mt][nt][3])
                    : "r"(a[mt][0]), "r"(a[mt][1]), "r"(a[mt][2]), "r"(a[mt][3]),
                      "r"(b0), "r"(b1));
            }
        }
    }

    // Streaming stores: 32B-sector-aligned float2 per lane, evict-first.
    float* gO = out + (size_t)h * MDIM * NDIM + (size_t)(bm * 128) * NDIM + bn * 128;
#pragma unroll
    for (int mt = 0; mt < 4; mt++) {
#pragma unroll
        for (int nt = 0; nt < 4; nt++) {
            int r0 = wm + mt * 16 + g;
            int c0 = wn + nt * 8 + t4 * 2;
            __stcs(reinterpret_cast<float2*>(&gO[(size_t)r0 * NDIM + c0]),
                   make_float2(acc[mt][nt][0], acc[mt][nt][1]));
            __stcs(reinterpret_cast<float2*>(&gO[(size_t)(r0 + 8) * NDIM + c0]),
                   make_float2(acc[mt][nt][2], acc[mt][nt][3]));
        }
    }
}

extern "C" void kernel_launch(void* const* d_in, const int* in_sizes, int n_in,
                              void* d_out, int out_size) {
    (void)in_sizes; (void)n_in; (void)out_size;
    const float* lhs = (const float*)d_in[0];  // [1,16,4096,64]
    const float* rhs = (const float*)d_in[1];  // [1,16,64,4096]
    float* out = (float*)d_out;                // [1,16,4096,4096]

    quant_all_kernel<<<QL_BLOCKS + QR_BLOCKS, 256>>>(lhs, rhs);

    dim3 grid(NDIM / 128, MDIM / 128, HEADS);
    bfp_gemm_kernel<<<grid, 256>>>(out);
}